// round 6
// baseline (speedup 1.0000x reference)
#include <cuda_runtime.h>
#include <math.h>

#define BB 16
#define TT_ 81
#define DD 128
#define HH 8
#define BT (BB*TT_)       // 1296

// scratch (no allocation allowed)
__device__ float g_bo[BB*HH*TT_*DD];
__device__ float g_G[BT*DD];

// ---------------- packed fp32x2 helpers (sm_100+) ----------------
static __device__ __forceinline__ unsigned long long add2(unsigned long long a,
                                                          unsigned long long b) {
    unsigned long long r;
    asm("add.rn.f32x2 %0, %1, %2;" : "=l"(r) : "l"(a), "l"(b));
    return r;
}
static __device__ __forceinline__ unsigned long long fma2(unsigned long long a,
                                                          unsigned long long b,
                                                          unsigned long long c) {
    unsigned long long r;
    asm("fma.rn.f32x2 %0, %1, %2, %3;" : "=l"(r) : "l"(a), "l"(b), "l"(c));
    return r;
}
static __device__ __forceinline__ unsigned long long pack2(float x) {
    unsigned long long r;
    asm("mov.b64 %0, {%1, %1};" : "=l"(r) : "f"(x));
    return r;
}
static __device__ __forceinline__ float2 unpack2(unsigned long long v) {
    float2 f;
    asm("mov.b64 {%0, %1}, %2;" : "=f"(f.x), "=f"(f.y) : "l"(v));
    return f;
}
#define ABS2MASK 0x7FFFFFFF7FFFFFFFULL

// ---- fused-kernel smem layout (float offsets) ----
#define XST_LD   90
#define OFF_XST  0                        // XsT [128][90] (t 81..89 zero); Msk overlay after P1
#define OFF_KT   (128*XST_LD)             // 11520  KT2: 64 d-pairs x 84 s (float2, NEGATED k)
#define OFF_QS   (OFF_KT + 64*84*2)       // 22272  Qs [81][128]
#define OFF_VS   (OFF_QS + TT_*DD)        // 32640  Vs [81][128]
#define LDS_S    84
#define OFF_S    (OFF_VS + TT_*DD)        // 43008  S  [81][84]  S[s][t]
#define OFF_WS   (OFF_S + TT_*LDS_S)      // 49812  Ws [2][16][256]  (k-local x n)
#define SMEM_FLOATS (OFF_WS + 2*16*256)   // 58004 floats = 232016 bytes

// ---------------------------------------------------------------------------
// Fused kernel: one block per (b,h), 512 threads.
//  P1: 14 warps x 6 t-rows, K-chunk 16, double-buffered -> 8 syncs total.
// ---------------------------------------------------------------------------
__global__ void __launch_bounds__(512, 1)
attn_fused(const float* __restrict__ x,
           const float* __restrict__ wqkv_w,
           const float* __restrict__ wqkv_b,
           const float* __restrict__ wk_w,
           const float* __restrict__ msk,
           const float* __restrict__ head_en,
           float* __restrict__ ap_out) {
    extern __shared__ float sm[];
    float* XsT = sm + OFF_XST;
    float* KT  = sm + OFF_KT;     // row stride (per d-pair) = 168 floats
    float* Qs  = sm + OFF_QS;
    float* Vs  = sm + OFF_VS;
    float* S   = sm + OFF_S;
    float* Ws  = sm + OFF_WS;
    float* Msk = sm + OFF_XST;    // overlay (valid after P1)

    const int b = blockIdx.x >> 3;
    const int h = blockIdx.x & 7;
    const int tid = threadIdx.x;

    // ---------------- P0: loads ----------------
    {
        const float4* x4  = (const float4*)(x + (size_t)b*TT_*DD);
        const float4* wk4 = (const float4*)(wk_w + h*DD);
        for (int i = tid; i < TT_*DD/4; i += 512) {
            float4 xv = x4[i];
            int t  = i >> 5;
            int d0 = (i & 31) * 4;
            XsT[(d0+0)*XST_LD + t] = xv.x;
            XsT[(d0+1)*XST_LD + t] = xv.y;
            XsT[(d0+2)*XST_LD + t] = xv.z;
            XsT[(d0+3)*XST_LD + t] = xv.w;
            float4 wv = wk4[i & 31];
            int dp = (i & 31) * 2;
            float2 k0, k1;
            k0.x = -(xv.x*wv.x); k0.y = -(xv.y*wv.y);
            k1.x = -(xv.z*wv.z); k1.y = -(xv.w*wv.w);
            *(float2*)&KT[(dp    )*168 + t*2] = k0;
            *(float2*)&KT[(dp + 1)*168 + t*2] = k1;
        }
        // zero XsT cols t = 81..89 for all 128 d
        for (int i = tid; i < 1152; i += 512) {
            int d = i / 9, t = 81 + (i % 9);
            XsT[d*XST_LD + t] = 0.f;
        }
        const float4 z4 = make_float4(0.f,0.f,0.f,0.f);
        for (int i = tid; i < TT_*LDS_S/4; i += 512)
            ((float4*)S)[i] = z4;
        for (int i = tid; i < 192; i += 512) {
            int dp = i / 3, s = 81 + (i % 3);
            *(float2*)&KT[dp*168 + s*2] = make_float2(0.f, 0.f);
        }
    }

    // W staging map: 16-k chunks, each thread 2 float4 (8 k-locals of one n row)
    const float* Wg = wqkv_w + ((size_t)h * 2 * DD) * DD;   // 256 rows x 128
    const int wrow = tid >> 1;              // 0..255  (output n)
    const int wkq  = (tid & 1) * 8;         // k-local 0 or 8

    {   // stage chunk 0
        float4 wa = *(const float4*)(Wg + wrow*DD + wkq);
        float4 wb = *(const float4*)(Wg + wrow*DD + wkq + 4);
        Ws[(wkq+0)*256 + wrow] = wa.x;
        Ws[(wkq+1)*256 + wrow] = wa.y;
        Ws[(wkq+2)*256 + wrow] = wa.z;
        Ws[(wkq+3)*256 + wrow] = wa.w;
        Ws[(wkq+4)*256 + wrow] = wb.x;
        Ws[(wkq+5)*256 + wrow] = wb.y;
        Ws[(wkq+6)*256 + wrow] = wb.z;
        Ws[(wkq+7)*256 + wrow] = wb.w;
    }
    __syncthreads();

    // ---------------- P1: QKV GEMM (14 warps x 6 t, chunk 16) ----------------
    const int wrp  = tid >> 5;              // warp id
    const int lane = tid & 31;
    const int t0 = wrp * 6;
    const int n0 = lane * 8;
    const bool gemm_act = (wrp < 14);

    unsigned long long acc[3][8];           // [t-pair][n]
#pragma unroll
    for (int i = 0; i < 3; i++)
#pragma unroll
        for (int j = 0; j < 8; j++) acc[i][j] = 0ULL;

    int buf = 0;
#pragma unroll 1
    for (int c = 0; c < 8; c++) {
        float4 wa, wb;
        if (c < 7) {
            wa = *(const float4*)(Wg + wrow*DD + (c+1)*16 + wkq);
            wb = *(const float4*)(Wg + wrow*DD + (c+1)*16 + wkq + 4);
        }
        if (gemm_act) {
            const float* Wb = Ws + buf*4096;
#pragma unroll
            for (int kk = 0; kk < 16; kk++) {
                const int k = c*16 + kk;
                unsigned long long a0 = *(const unsigned long long*)&XsT[k*XST_LD + t0];
                unsigned long long a1 = *(const unsigned long long*)&XsT[k*XST_LD + t0 + 2];
                unsigned long long a2 = *(const unsigned long long*)&XsT[k*XST_LD + t0 + 4];
                float4 w0 = *(const float4*)&Wb[kk*256 + n0];
                float4 w1 = *(const float4*)&Wb[kk*256 + n0 + 4];
                unsigned long long wp[8];
                wp[0] = pack2(w0.x); wp[1] = pack2(w0.y);
                wp[2] = pack2(w0.z); wp[3] = pack2(w0.w);
                wp[4] = pack2(w1.x); wp[5] = pack2(w1.y);
                wp[6] = pack2(w1.z); wp[7] = pack2(w1.w);
#pragma unroll
                for (int j = 0; j < 8; j++) {
                    acc[0][j] = fma2(a0, wp[j], acc[0][j]);
                    acc[1][j] = fma2(a1, wp[j], acc[1][j]);
                    acc[2][j] = fma2(a2, wp[j], acc[2][j]);
                }
            }
        }
        if (c < 7) {
            float* Wb2 = Ws + (buf^1)*4096;
            Wb2[(wkq+0)*256 + wrow] = wa.x;
            Wb2[(wkq+1)*256 + wrow] = wa.y;
            Wb2[(wkq+2)*256 + wrow] = wa.z;
            Wb2[(wkq+3)*256 + wrow] = wa.w;
            Wb2[(wkq+4)*256 + wrow] = wb.x;
            Wb2[(wkq+5)*256 + wrow] = wb.y;
            Wb2[(wkq+6)*256 + wrow] = wb.z;
            Wb2[(wkq+7)*256 + wrow] = wb.w;
        }
        __syncthreads();
        buf ^= 1;
    }

    // epilogue: +bias, q -> Qs ; v -> Vs * head_en
    if (gemm_act) {
        const bool isv = (lane >= 16);
        const int d0 = (lane & 15) * 8;
        const float sc = isv ? head_en[h] : 1.0f;
        float* dst = isv ? Vs : Qs;
        float4 bia0 = *(const float4*)(wqkv_b + h*256 + n0);
        float4 bia1 = *(const float4*)(wqkv_b + h*256 + n0 + 4);
#pragma unroll
        for (int tp = 0; tp < 3; tp++) {
            float2 p[8];
#pragma unroll
            for (int j = 0; j < 8; j++) p[j] = unpack2(acc[tp][j]);
            int ta = t0 + 2*tp;
            int tb = ta + 1;
            if (ta < TT_) {
                float4 oa0, oa1;
                oa0.x = (p[0].x + bia0.x)*sc;  oa0.y = (p[1].x + bia0.y)*sc;
                oa0.z = (p[2].x + bia0.z)*sc;  oa0.w = (p[3].x + bia0.w)*sc;
                oa1.x = (p[4].x + bia1.x)*sc;  oa1.y = (p[5].x + bia1.y)*sc;
                oa1.z = (p[6].x + bia1.z)*sc;  oa1.w = (p[7].x + bia1.w)*sc;
                *(float4*)&dst[ta*DD + d0]     = oa0;
                *(float4*)&dst[ta*DD + d0 + 4] = oa1;
            }
            if (tb < TT_) {
                float4 ob0, ob1;
                ob0.x = (p[0].y + bia0.x)*sc;  ob0.y = (p[1].y + bia0.y)*sc;
                ob0.z = (p[2].y + bia0.z)*sc;  ob0.w = (p[3].y + bia0.w)*sc;
                ob1.x = (p[4].y + bia1.x)*sc;  ob1.y = (p[5].y + bia1.y)*sc;
                ob1.z = (p[6].y + bia1.z)*sc;  ob1.w = (p[7].y + bia1.w)*sc;
                *(float4*)&dst[tb*DD + d0]     = ob0;
                *(float4*)&dst[tb*DD + d0 + 4] = ob1;
            }
        }
    }
    __syncthreads();

    // ---------------- P2: scores (+ msk prefetch by warps 14/15) ----------------
    const float scale = 0.08838834764831843f;   // 1/sqrt(128)
    if (tid >= 448) {
        const float* mg = msk + (size_t)h * TT_ * TT_;
        for (int i = tid - 448; i < TT_*TT_; i += 64) Msk[i] = mg[i];
    } else if (tid < 441) {
        const int t0s = (tid / 21) * 4;
        const int s0 = (tid % 21) * 4;
        int ti[4];
#pragma unroll
        for (int i = 0; i < 4; i++) ti[i] = min(t0s + i, TT_ - 1);

        unsigned long long sacc[4][4];
#pragma unroll
        for (int i = 0; i < 4; i++)
#pragma unroll
            for (int j = 0; j < 4; j++) sacc[i][j] = 0ULL;

#pragma unroll 1
        for (int d = 0; d < DD; d += 4) {
            const int dp = d >> 1;
            ulonglong2 q[4];
#pragma unroll
            for (int i = 0; i < 4; i++)
                q[i] = *(const ulonglong2*)&Qs[ti[i]*DD + d];
            ulonglong2 ka = *(const ulonglong2*)&KT[(dp  )*168 + s0*2];
            ulonglong2 kb = *(const ulonglong2*)&KT[(dp  )*168 + s0*2 + 4];
            ulonglong2 kc = *(const ulonglong2*)&KT[(dp+1)*168 + s0*2];
            ulonglong2 kd = *(const ulonglong2*)&KT[(dp+1)*168 + s0*2 + 4];
#pragma unroll
            for (int i = 0; i < 4; i++) {
                unsigned long long u;
                u = add2(q[i].x, ka.x) & ABS2MASK;  sacc[i][0] = add2(sacc[i][0], u);
                u = add2(q[i].y, kc.x) & ABS2MASK;  sacc[i][0] = add2(sacc[i][0], u);
                u = add2(q[i].x, ka.y) & ABS2MASK;  sacc[i][1] = add2(sacc[i][1], u);
                u = add2(q[i].y, kc.y) & ABS2MASK;  sacc[i][1] = add2(sacc[i][1], u);
                u = add2(q[i].x, kb.x) & ABS2MASK;  sacc[i][2] = add2(sacc[i][2], u);
                u = add2(q[i].y, kd.x) & ABS2MASK;  sacc[i][2] = add2(sacc[i][2], u);
                u = add2(q[i].x, kb.y) & ABS2MASK;  sacc[i][3] = add2(sacc[i][3], u);
                u = add2(q[i].y, kd.y) & ABS2MASK;  sacc[i][3] = add2(sacc[i][3], u);
            }
        }
#pragma unroll
        for (int i = 0; i < 4; i++) {
            if (t0s + i >= TT_) continue;
#pragma unroll
            for (int j = 0; j < 4; j++) {
                if (s0 + j >= TT_) continue;
                float2 f = unpack2(sacc[i][j]);
                S[(s0 + j)*LDS_S + (t0s + i)] = -(f.x + f.y) * scale;
            }
        }
    }
    __syncthreads();

    // ---------------- P3: softmax over s (quad-parallel per t) ----------------
    if (tid < 352) {
        const int t  = tid >> 2;
        const int l4 = tid & 3;
        const bool valid = (t < TT_);
        const int sBeg = l4 * 21;
        const int sEnd = valid ? min(sBeg + 21, TT_) : sBeg;

        float mx = -1e30f;
        for (int s = sBeg; s < sEnd; s++) mx = fmaxf(mx, S[s*LDS_S + t]);
        mx = fmaxf(mx, __shfl_xor_sync(0xFFFFFFFFu, mx, 1));
        mx = fmaxf(mx, __shfl_xor_sync(0xFFFFFFFFu, mx, 2));

        float sum = 0.f;
        for (int s = sBeg; s < sEnd; s++) {
            float e = __expf(S[s*LDS_S + t] - mx);
            sum += e;
            S[s*LDS_S + t] = e;
        }
        sum += __shfl_xor_sync(0xFFFFFFFFu, sum, 1);
        sum += __shfl_xor_sync(0xFFFFFFFFu, sum, 2);
        float inv = 1.f / sum;

        for (int s = sBeg; s < sEnd; s++) {
            float mval = Msk[t*TT_ + s];
            float a = S[s*LDS_S + t] * inv * mval;
            S[s*LDS_S + t] = a;
            if (b == 0)
                ap_out[((size_t)t*TT_ + s)*HH + h] = a - 1.f + mval;
        }
    }
    __syncthreads();

    // ---------------- P4: AV GEMM -> g_bo ----------------
    float* bo = g_bo + (((size_t)b*HH + h)*TT_)*DD;
    if (tid < 336) {                      // 21 t-tiles x 16 d-tiles
        int t0a = (tid >> 4) * 4;
        int d0 = (tid & 15) * 8;
        unsigned long long av[4][4];
#pragma unroll
        for (int i = 0; i < 4; i++)
#pragma unroll
            for (int j = 0; j < 4; j++) av[i][j] = 0ULL;

#pragma unroll 2
        for (int s = 0; s < TT_; s++) {
            float4 a4 = *(const float4*)&S[s*LDS_S + t0a];   // pad cols are 0
            ulonglong2 v0 = *(const ulonglong2*)&Vs[s*DD + d0];
            ulonglong2 v1 = *(const ulonglong2*)&Vs[s*DD + d0 + 4];
            unsigned long long a0 = pack2(a4.x);
            unsigned long long a1 = pack2(a4.y);
            unsigned long long a2v = pack2(a4.z);
            unsigned long long a3 = pack2(a4.w);
            av[0][0] = fma2(a0, v0.x, av[0][0]);
            av[0][1] = fma2(a0, v0.y, av[0][1]);
            av[0][2] = fma2(a0, v1.x, av[0][2]);
            av[0][3] = fma2(a0, v1.y, av[0][3]);
            av[1][0] = fma2(a1, v0.x, av[1][0]);
            av[1][1] = fma2(a1, v0.y, av[1][1]);
            av[1][2] = fma2(a1, v1.x, av[1][2]);
            av[1][3] = fma2(a1, v1.y, av[1][3]);
            av[2][0] = fma2(a2v, v0.x, av[2][0]);
            av[2][1] = fma2(a2v, v0.y, av[2][1]);
            av[2][2] = fma2(a2v, v1.x, av[2][2]);
            av[2][3] = fma2(a2v, v1.y, av[2][3]);
            av[3][0] = fma2(a3, v0.x, av[3][0]);
            av[3][1] = fma2(a3, v0.y, av[3][1]);
            av[3][2] = fma2(a3, v1.x, av[3][2]);
            av[3][3] = fma2(a3, v1.y, av[3][3]);
        }
#pragma unroll
        for (int i = 0; i < 4; i++) {
            int t = t0a + i;
            if (t >= TT_) continue;
            float2 p0 = unpack2(av[i][0]);
            float2 p1 = unpack2(av[i][1]);
            float2 p2 = unpack2(av[i][2]);
            float2 p3 = unpack2(av[i][3]);
            float4 o0 = make_float4(p0.x, p0.y, p1.x, p1.y);
            float4 o1 = make_float4(p2.x, p2.y, p3.x, p3.y);
            *(float4*)&bo[(size_t)t*DD + d0]     = o0;
            *(float4*)&bo[(size_t)t*DD + d0 + 4] = o1;
        }
    }
}

// ---------------------------------------------------------------------------
// Kernel 2a: G[m][d] = qgelu(sum_h bo[b][h][t][d])
// ---------------------------------------------------------------------------
__device__ __forceinline__ float qgelu4(float s) {
    float u = s + 4.f;
    return u / (1.f + __expf(-1.702f * u)) - 4.f;
}

__global__ void __launch_bounds__(128) reduce_gelu_kernel() {
    int idx = blockIdx.x * 128 + threadIdx.x;   // 0..41471
    int m  = idx >> 5;
    int kq = idx & 31;
    int bb = m / TT_, t = m - bb * TT_;
    const float4* base = (const float4*)g_bo + ((size_t)(bb*HH)*TT_ + t)*32 + kq;
    float s0 = 0.f, s1 = 0.f, s2 = 0.f, s3 = 0.f;
#pragma unroll
    for (int hh = 0; hh < HH; hh++) {
        float4 v = base[(size_t)hh*TT_*32];
        s0 += v.x; s1 += v.y; s2 += v.z; s3 += v.w;
    }
    float4 g;
    g.x = qgelu4(s0); g.y = qgelu4(s1); g.z = qgelu4(s2); g.w = qgelu4(s3);
    ((float4*)g_G)[(size_t)m*32 + kq] = g;
}

// ---------------------------------------------------------------------------
// Kernel 2b: out = x + G@Wf^T + bf.  162 blocks (16m x 64n), 256 threads.
// ---------------------------------------------------------------------------
__global__ void __launch_bounds__(256) fanout_kernel(const float* __restrict__ x,
                                                     const float* __restrict__ Wf,
                                                     const float* __restrict__ bf,
                                                     float* __restrict__ out) {
    extern __shared__ float sm[];
    float* Ws = sm;                 // [128][64]  Ws[k][n]
    float* Gs = sm + 128*64;        // [128][17]  Gs[k*17 + m]
    const int LDG_ = 17;
    const int mtile = blockIdx.x >> 1;
    const int half  = blockIdx.x & 1;
    const int m0 = mtile * 16;
    const int nbase = half * 64;
    const int tid = threadIdx.x;

    {
        int n  = tid & 63;
        int k4 = tid >> 6;              // 0..3
        const float* wr = Wf + (size_t)(nbase + n) * DD;
#pragma unroll
        for (int p = 0; p < 8; p++) {
            int kq = p * 4 + k4;        // 0..31
            float4 w = *(const float4*)(wr + kq * 4);
            Ws[(kq*4+0)*64 + n] = w.x;
            Ws[(kq*4+1)*64 + n] = w.y;
            Ws[(kq*4+2)*64 + n] = w.z;
            Ws[(kq*4+3)*64 + n] = w.w;
        }
    }
    {
#pragma unroll
        for (int p = 0; p < 2; p++) {
            int i  = p * 256 + tid;     // 0..511
            int ml = i >> 5;
            int kq = i & 31;
            float4 g = ((const float4*)g_G)[(size_t)(m0 + ml)*32 + kq];
            Gs[(kq*4+0)*LDG_ + ml] = g.x;
            Gs[(kq*4+1)*LDG_ + ml] = g.y;
            Gs[(kq*4+2)*LDG_ + ml] = g.z;
            Gs[(kq*4+3)*LDG_ + ml] = g.w;
        }
    }
    __syncthreads();

    const int m_ = tid >> 4;            // 0..15
    const int n0 = (tid & 15) * 4;      // 0..60
    float a0 = 0.f, a1 = 0.f, a2 = 0.f, a3 = 0.f;
#pragma unroll 8
    for (int k = 0; k < 128; k++) {
        float g = Gs[k*LDG_ + m_];
        float4 w = *(const float4*)&Ws[k*64 + n0];
        a0 += g * w.x; a1 += g * w.y; a2 += g * w.z; a3 += g * w.w;
    }
    int m = m0 + m_;
    int ng = nbase + n0;
    float4 xv = *(const float4*)&x[(size_t)m*DD + ng];
    float4 bv = *(const float4*)&bf[ng];
    float4 o;
    o.x = xv.x + a0 + bv.x;
    o.y = xv.y + a1 + bv.y;
    o.z = xv.z + a2 + bv.z;
    o.w = xv.w + a3 + bv.w;
    *(float4*)&out[(size_t)m*DD + ng] = o;
}

// ---------------------------------------------------------------------------
extern "C" void kernel_launch(void* const* d_in, const int* in_sizes, int n_in,
                              void* d_out, int out_size) {
    const float* x        = (const float*)d_in[0];
    const float* msk      = (const float*)d_in[1];
    const float* wqkv_w   = (const float*)d_in[2];
    const float* wqkv_b   = (const float*)d_in[3];
    const float* wk_w     = (const float*)d_in[4];
    const float* fanout_w = (const float*)d_in[5];
    const float* fanout_b = (const float*)d_in[6];
    const float* head_en  = (const float*)d_in[7];

    float* out = (float*)d_out;
    float* ap_out = out + (size_t)BT * DD;   // 165888 onward

    const int smemA = SMEM_FLOATS * 4;                   // 232016
    const int smem3 = (128*64 + 128*17) * 4 + 16;        // ~41.5KB

    cudaFuncSetAttribute(attn_fused,    cudaFuncAttributeMaxDynamicSharedMemorySize, smemA);
    cudaFuncSetAttribute(fanout_kernel, cudaFuncAttributeMaxDynamicSharedMemorySize, smem3);

    attn_fused<<<BB * HH, 512, smemA>>>(x, wqkv_w, wqkv_b, wk_w, msk, head_en, ap_out);

    reduce_gelu_kernel<<<324, 128>>>();

    fanout_kernel<<<162, 256, smem3>>>(x, fanout_w, fanout_b, out);
}